// round 8
// baseline (speedup 1.0000x reference)
#include <cuda_runtime.h>
#include <math.h>

#define HH 1024
#define WW 1024
#define BBATCH 8
#define PLANE (HH*WW)          // 1<<20
#define NPIX (BBATCH*PLANE)    // 8<<20

__device__ float g_E[NPIX];    // edge_soft
__device__ float g_A[NPIX];    // ping
__device__ float g_B2[NPIX];   // pong
__device__ float g_acc[3];     // mask_sum, chroma_sum, hue_sum

__device__ __forceinline__ float4 ld4(const float* p){ return *reinterpret_cast<const float4*>(p); }
__device__ __forceinline__ void st4(float* p, float4 v){ *reinterpret_cast<float4*>(p) = v; }
__device__ __forceinline__ float2 ld2(const float* p){ return *reinterpret_cast<const float2*>(p); }
__device__ __forceinline__ void st2(float* p, float2 v){ *reinterpret_cast<float2*>(p) = v; }

template<bool M>
__device__ __forceinline__ float rop(float a, float b){ return M ? fmaxf(a,b) : fminf(a,b); }
template<bool M>
__device__ __forceinline__ float2 rop2(float2 a, float2 b){
    float2 r; r.x = rop<M>(a.x,b.x); r.y = rop<M>(a.y,b.y); return r;
}

// ---------------------------------------------------------------------------
// Pass 1: Sobel edge (zero-padded), |gx|+|gy|, max over channels, clip(/0.5,0,1)
// ---------------------------------------------------------------------------
#define ET 8

__device__ __forceinline__ void load_row6(const float* p, int x0, float* r)
{
    r[0] = (x0 > 0) ? p[x0-1] : 0.f;
    float4 v = ld4(p + x0); r[1]=v.x; r[2]=v.y; r[3]=v.z; r[4]=v.w;
    r[5] = (x0+4 < WW) ? p[x0+4] : 0.f;
}

__device__ __forceinline__ void zero_row6(float* r)
{
    #pragma unroll
    for (int i=0;i<6;i++) r[i]=0.f;
}

__global__ void __launch_bounds__(256) edge_kernel(const float* __restrict__ t)
{
    int x0  = threadIdx.x << 2;
    int grp = blockIdx.x;
    int b   = grp / (HH/ET);
    int y0  = (grp % (HH/ET)) * ET;

    float g[ET][4];
    #pragma unroll
    for (int k=0;k<ET;k++){ g[k][0]=0.f; g[k][1]=0.f; g[k][2]=0.f; g[k][3]=0.f; }

    #pragma unroll
    for (int c = 0; c < 3; c++) {
        const float* p = t + (size_t)b*3*PLANE + (size_t)c*PLANE;
        float row[3][6];
        if (y0 > 0) load_row6(p + (size_t)(y0-1)*WW, x0, row[0]);
        else        zero_row6(row[0]);
        load_row6(p + (size_t)y0*WW, x0, row[1]);

        #pragma unroll
        for (int k = 0; k < ET; k++) {
            int ynext = y0 + k + 1;
            float* nr = row[(k+2)%3];
            if (ynext <= HH-1) load_row6(p + (size_t)ynext*WW, x0, nr);
            else               zero_row6(nr);

            const float* a  = row[ k   %3];
            const float* bm = row[(k+1)%3];
            const float* cm = row[(k+2)%3];

            float s[6], d[6];
            #pragma unroll
            for (int i=0;i<6;i++){ s[i] = fmaf(2.f, bm[i], a[i]+cm[i]); d[i] = cm[i]-a[i]; }
            #pragma unroll
            for (int j=0;j<4;j++){
                float gx = s[j+2] - s[j];
                float gy = fmaf(2.f, d[j+1], d[j]+d[j+2]);
                g[k][j] = fmaxf(g[k][j], fabsf(gx) + fabsf(gy));
            }
        }
    }

    float* obase = g_E + (size_t)b*PLANE + x0;
    #pragma unroll
    for (int k=0;k<ET;k++){
        float4 o;
        o.x = fminf(g[k][0]*2.f, 1.f);
        o.y = fminf(g[k][1]*2.f, 1.f);
        o.z = fminf(g[k][2]*2.f, 1.f);
        o.w = fminf(g[k][3]*2.f, 1.f);
        st4(obase + (size_t)(y0+k)*WW, o);
    }
}

// ---------------------------------------------------------------------------
// Horizontal 11-tap pool, 16 outputs/thread: 8 aligned ld4 (MLP=8) covering
// a[0..31] = cols c0-8 .. c0+23, then log-tree sliding max/min.
// out[j] (j=0..15) = reduce over a[j+3 .. j+13]  (cols c0+j-5 .. c0+j+5)
// ---------------------------------------------------------------------------
template<bool M>
__device__ __forceinline__ void hpool16_body(const float* __restrict__ in, float* __restrict__ out)
{
    int t   = threadIdx.x;
    int row = blockIdx.x * 4 + (t >> 6);
    int c0  = (t & 63) << 4;
    const float* p = in + (size_t)row*WW;

    float a[32];
    if (c0 >= 8 && c0 + 24 <= WW) {
        #pragma unroll
        for (int k = 0; k < 8; k++) {
            float4 v = ld4(p + c0 - 8 + k*4);
            a[k*4+0]=v.x; a[k*4+1]=v.y; a[k*4+2]=v.z; a[k*4+3]=v.w;
        }
    } else {
        #pragma unroll
        for (int i = 0; i < 32; i++) {
            int xx = c0 - 8 + i; xx = xx < 0 ? 0 : (xx > WW-1 ? WW-1 : xx);
            a[i] = p[xx];
        }
    }

    float m2[27], m4[23], m8[19];
    #pragma unroll
    for (int i = 3; i <= 26; i++) m2[i] = rop<M>(a[i],  a[i+1]);
    #pragma unroll
    for (int i = 3; i <= 22; i++) m4[i] = rop<M>(m2[i], m2[i+2]);
    #pragma unroll
    for (int i = 3; i <= 18; i++) m8[i] = rop<M>(m4[i], m4[i+4]);

    float* q = out + (size_t)row*WW + c0;
    #pragma unroll
    for (int k = 0; k < 4; k++) {
        float4 o;
        o.x = rop<M>(m8[4*k+3], rop<M>(m2[4*k+11], a[4*k+13]));
        o.y = rop<M>(m8[4*k+4], rop<M>(m2[4*k+12], a[4*k+14]));
        o.z = rop<M>(m8[4*k+5], rop<M>(m2[4*k+13], a[4*k+15]));
        o.w = rop<M>(m8[4*k+6], rop<M>(m2[4*k+14], a[4*k+16]));
        st4(q + 4*k, o);
    }
}

__global__ void __launch_bounds__(256) k_hmax11(){ hpool16_body<true >(g_E,  g_A); }
__global__ void __launch_bounds__(256) k_hmin11(){ hpool16_body<false>(g_B2, g_A); }

// ---------------------------------------------------------------------------
// Vertical 11-tap pool, 8 output rows/thread: 18 independent ld2 (MLP=18),
// then log-tree sliding max/min. out[j] = reduce over rows a[j..j+10].
// ---------------------------------------------------------------------------
template<bool M>
__device__ __forceinline__ void vpool8_body(const float* __restrict__ in, float* __restrict__ out)
{
    int t   = threadIdx.x;
    int g   = blockIdx.x;
    int b   = g >> 8;              // 256 groups per batch
    int rem = g & 255;
    int yg  = rem >> 1;            // 0..127
    int xg  = rem & 1;
    int y0  = yg * 8;
    int x0  = xg*512 + t*2;
    const float* base  = in  + (size_t)b*PLANE + x0;
    float*       obase = out + (size_t)b*PLANE + x0;

    float2 a[18];
    #pragma unroll
    for (int i = 0; i < 18; i++) {
        int yy = y0 - 5 + i; yy = yy < 0 ? 0 : (yy > HH-1 ? HH-1 : yy);
        a[i] = ld2(base + (size_t)yy*WW);
    }

    float2 m2[16], m4[12], m8[8];
    #pragma unroll
    for (int i = 0; i < 16; i++) m2[i] = rop2<M>(a[i],  a[i+1]);
    #pragma unroll
    for (int i = 0; i < 12; i++) m4[i] = rop2<M>(m2[i], m2[i+2]);
    #pragma unroll
    for (int i = 0; i <  8; i++) m8[i] = rop2<M>(m4[i], m4[i+4]);

    #pragma unroll
    for (int j = 0; j < 8; j++) {
        float2 o = rop2<M>(m8[j], rop2<M>(m2[j+8], a[j+10]));
        st2(obase + (size_t)(y0+j)*WW, o);
    }
}

__global__ void __launch_bounds__(256) k_vmax11(){ vpool8_body<true >(g_A, g_B2); }
__global__ void __launch_bounds__(256) k_vmin11(){ vpool8_body<false>(g_A, g_B2); }

// ---------------------------------------------------------------------------
// Fused final kernel: mask = relu(closed-edge) -> 5x5 max -> masked OKLab loss.
// ---------------------------------------------------------------------------
__device__ __forceinline__ float4 maskrow_h5(const float* __restrict__ pc,
                                             const float* __restrict__ pe, int x0)
{
    float m[8];   // positions x0-2 .. x0+5
    if (x0 >= 4 && x0 <= WW-8) {
        float4 c0 = ld4(pc+x0-4), c1 = ld4(pc+x0), c2 = ld4(pc+x0+4);
        float4 e0 = ld4(pe+x0-4), e1 = ld4(pe+x0), e2 = ld4(pe+x0+4);
        m[0]=fmaxf(c0.z-e0.z,0.f); m[1]=fmaxf(c0.w-e0.w,0.f);
        m[2]=fmaxf(c1.x-e1.x,0.f); m[3]=fmaxf(c1.y-e1.y,0.f);
        m[4]=fmaxf(c1.z-e1.z,0.f); m[5]=fmaxf(c1.w-e1.w,0.f);
        m[6]=fmaxf(c2.x-e2.x,0.f); m[7]=fmaxf(c2.y-e2.y,0.f);
    } else {
        #pragma unroll
        for (int i=0;i<8;i++){
            int xx = x0-2+i; xx = xx < 0 ? 0 : (xx > WW-1 ? WW-1 : xx);
            m[i] = fmaxf(pc[xx]-pe[xx], 0.f);
        }
    }
    float C   = fmaxf(m[3], m[4]);
    float t12 = fmaxf(m[1], m[2]);
    float t56 = fmaxf(m[5], m[6]);
    float4 o;
    o.x = fmaxf(C, fmaxf(m[0], t12));
    o.y = fmaxf(C, fmaxf(t12,  m[5]));
    o.z = fmaxf(fmaxf(C, m[2]), t56);
    o.w = fmaxf(fmaxf(C, m[7]), t56);
    return o;
}

__device__ __forceinline__ float s2l(float x)
{
    x = fminf(fmaxf(x, 0.f), 1.f);
    return (x <= 0.04045f) ? x * (1.f/12.92f)
                           : __powf((x + 0.055f) * (1.f/1.055f), 2.4f);
}

__device__ __forceinline__ void oklab_ab(float r, float g, float bl, float& A, float& Bc)
{
    float lr = s2l(r), lg = s2l(g), lb = s2l(bl);
    float l = 0.4122214708f*lr + 0.5363325363f*lg + 0.0514459929f*lb;
    float m = 0.2119034982f*lr + 0.6806995451f*lg + 0.1073969566f*lb;
    float s = 0.0883024619f*lr + 0.2817188376f*lg + 0.6299787005f*lb;
    l = cbrtf(fmaxf(l, 1e-10f));
    m = cbrtf(fmaxf(m, 1e-10f));
    s = cbrtf(fmaxf(s, 1e-10f));
    A  = 1.9779984951f*l - 2.428592205f*m + 0.4505937099f*s;
    Bc = 0.0259040371f*l + 0.7827717662f*m - 0.808675766f*s;
}

#define MT 8

__global__ void __launch_bounds__(256) k_maskloss(const float* __restrict__ pred,
                                                  const float* __restrict__ tgt)
{
    int x0   = threadIdx.x << 2;
    int grp  = blockIdx.x;
    int b    = grp / (HH/MT);
    int y0   = (grp % (HH/MT)) * MT;
    const float* cb = g_B2 + (size_t)b*PLANE;   // closed
    const float* eb = g_E  + (size_t)b*PLANE;   // edge

    float msum = 0.f, chroma = 0.f, hue = 0.f;

    float4 r[5];
    #pragma unroll
    for (int i = 0; i < 4; i++) {
        int yy = y0 - 2 + i; yy = yy < 0 ? 0 : yy;
        r[i] = maskrow_h5(cb + (size_t)yy*WW, eb + (size_t)yy*WW, x0);
    }
    #pragma unroll
    for (int k = 0; k < MT; k++) {
        int yy = y0 + k + 2; yy = yy > HH-1 ? HH-1 : yy;
        r[(4+k) % 5] = maskrow_h5(cb + (size_t)yy*WW, eb + (size_t)yy*WW, x0);
        float4 o = r[0];
        #pragma unroll
        for (int i=1;i<5;i++){
            o.x = fmaxf(o.x, r[i].x); o.y = fmaxf(o.y, r[i].y);
            o.z = fmaxf(o.z, r[i].z); o.w = fmaxf(o.w, r[i].w);
        }
        msum += (o.x + o.y) + (o.z + o.w);
        if (o.x > 0.f || o.y > 0.f || o.z > 0.f || o.w > 0.f) {
            size_t base = (size_t)b*3*PLANE + (size_t)(y0+k)*WW + x0;
            float mv[4] = {o.x, o.y, o.z, o.w};
            #pragma unroll 1
            for (int j = 0; j < 4; j++) {
                float m = mv[j];
                if (m > 0.f) {
                    float pa,pb,ta,tb;
                    oklab_ab(pred[base+j], pred[base+j+PLANE], pred[base+j+2*PLANE], pa, pb);
                    oklab_ab(tgt [base+j], tgt [base+j+PLANE], tgt [base+j+2*PLANE], ta, tb);
                    float Cp = sqrtf(fmaf(pa,pa, pb*pb) + 1e-12f);
                    float Cg = sqrtf(fmaf(ta,ta, tb*tb) + 1e-12f);
                    chroma += fabsf(Cp - Cg) * m;
                    float cosd = (pa*ta + pb*tb) / (Cp*Cg + 1e-12f);
                    cosd = fminf(fmaxf(cosd, -1.f), 1.f);
                    hue += fmaxf(Cg, 0.01f) * (1.f - cosd) * m;
                }
            }
        }
    }

    #pragma unroll
    for (int o=16; o; o>>=1){
        msum   += __shfl_xor_sync(0xffffffffu, msum,   o);
        chroma += __shfl_xor_sync(0xffffffffu, chroma, o);
        hue    += __shfl_xor_sync(0xffffffffu, hue,    o);
    }
    __shared__ float sm[3][8];
    int w = threadIdx.x >> 5, lane = threadIdx.x & 31;
    if (lane == 0){ sm[0][w]=msum; sm[1][w]=chroma; sm[2][w]=hue; }
    __syncthreads();
    if (threadIdx.x == 0){
        float a=0.f, c=0.f, h=0.f;
        #pragma unroll
        for (int i=0;i<8;i++){ a+=sm[0][i]; c+=sm[1][i]; h+=sm[2][i]; }
        atomicAdd(&g_acc[0], a);
        atomicAdd(&g_acc[1], c);
        atomicAdd(&g_acc[2], h);
    }
}

__global__ void k_zero(){ if (threadIdx.x < 3) g_acc[threadIdx.x] = 0.f; }

__global__ void k_fin(float* out)
{
    float ms = fmaxf(g_acc[0], 1.f);
    out[0] = g_acc[1]/ms + 2.f*(g_acc[2]/ms);
}

// ---------------------------------------------------------------------------
extern "C" void kernel_launch(void* const* d_in, const int* in_sizes, int n_in,
                              void* d_out, int out_size)
{
    const float* pred = (const float*)d_in[0];
    const float* tgt  = (const float*)d_in[1];
    float* out = (float*)d_out;

    const int egrid = BBATCH*HH/ET;     // 1024
    const int hgrid = BBATCH*HH/4;      // 2048 (4 rows per block)
    const int vgrid = BBATCH*(HH/8)*2;  // 2048 (8 rows x 512 cols per block)
    const int mgrid = BBATCH*HH/MT;     // 1024
    dim3 blk(256);

    k_zero     <<<1, 32>>>();
    edge_kernel<<<egrid, blk>>>(tgt);       // target -> g_E
    k_hmax11   <<<hgrid, blk>>>();          // g_E  -> g_A
    k_vmax11   <<<vgrid, blk>>>();          // g_A  -> g_B2 (dilated)
    k_hmin11   <<<hgrid, blk>>>();          // g_B2 -> g_A
    k_vmin11   <<<vgrid, blk>>>();          // g_A  -> g_B2 (closed)
    k_maskloss <<<mgrid, blk>>>(pred, tgt); // (g_B2, g_E, pred, tgt) -> g_acc
    k_fin      <<<1, 1>>>(out);
}